// round 1
// baseline (speedup 1.0000x reference)
#include <cuda_runtime.h>
#include <cuda_bf16.h>
#include <math.h>

#define NN   100000
#define M3   3
#define DIN  128
#define DH   64
#define NE   1600000

// ---- scratch (static device allocations; no cudaMalloc allowed) ----
__device__ float g_proj[(size_t)M3 * NN * DH];   // [m][n][h]
__device__ float g_h   [(size_t)M3 * NN * DH];   // agg, then post-prelu h
__device__ float g_deg [(size_t)M3 * NN];
__device__ float g_logits[M3];
__device__ float g_beta[M3];

// ---------------------------------------------------------------------------
// Kernel 0: zero agg/deg/logits
// ---------------------------------------------------------------------------
__global__ void zero_kernel() {
    size_t i = (size_t)blockIdx.x * blockDim.x + threadIdx.x;
    size_t tot4 = (size_t)M3 * NN * DH / 4;           // 4.8M float4
    if (i < tot4) ((float4*)g_h)[i] = make_float4(0.f, 0.f, 0.f, 0.f);
    if (i < (size_t)M3 * NN / 4) ((float4*)g_deg)[i] = make_float4(0.f, 0.f, 0.f, 0.f);
    if (i == 0) { g_logits[0] = 0.f; g_logits[1] = 0.f; g_logits[2] = 0.f; }
}

// ---------------------------------------------------------------------------
// Kernel 1: proj[m][n][h] = sum_d feats[m][n][d] * W[m][d][h]
// 64x64 output tile per block, 256 threads, 4x4 microtile, k-chunks of 64.
// ---------------------------------------------------------------------------
__global__ __launch_bounds__(256) void proj_kernel(const float* __restrict__ feats,
                                                   const float* __restrict__ W) {
    __shared__ __align__(16) float sF[64][65];   // [node][k] padded
    __shared__ __align__(16) float sW[64][DH];   // [k][h]
    const int m  = blockIdx.y;
    const int n0 = blockIdx.x * 64;
    const int tid = threadIdx.x;
    const int tx = tid & 15, ty = tid >> 4;

    const float* fbase = feats + (size_t)m * NN * DIN;
    const float* wbase = W + (size_t)m * DIN * DH;

    float acc[4][4] = {};
    for (int kk = 0; kk < DIN; kk += 64) {
        for (int i = tid; i < 64 * 64; i += 256) {
            int r = i >> 6, c = i & 63;
            int n = n0 + r;
            sF[r][c] = (n < NN) ? fbase[(size_t)n * DIN + kk + c] : 0.f;
        }
        for (int i = tid; i < 64 * DH; i += 256) {
            int r = i >> 6, c = i & 63;
            sW[r][c] = wbase[(size_t)(kk + r) * DH + c];
        }
        __syncthreads();
#pragma unroll
        for (int k = 0; k < 64; k++) {
            float a0 = sF[ty * 4 + 0][k];
            float a1 = sF[ty * 4 + 1][k];
            float a2 = sF[ty * 4 + 2][k];
            float a3 = sF[ty * 4 + 3][k];
            float4 bv = *(const float4*)&sW[k][tx * 4];
            acc[0][0] += a0 * bv.x; acc[0][1] += a0 * bv.y; acc[0][2] += a0 * bv.z; acc[0][3] += a0 * bv.w;
            acc[1][0] += a1 * bv.x; acc[1][1] += a1 * bv.y; acc[1][2] += a1 * bv.z; acc[1][3] += a1 * bv.w;
            acc[2][0] += a2 * bv.x; acc[2][1] += a2 * bv.y; acc[2][2] += a2 * bv.z; acc[2][3] += a2 * bv.w;
            acc[3][0] += a3 * bv.x; acc[3][1] += a3 * bv.y; acc[3][2] += a3 * bv.z; acc[3][3] += a3 * bv.w;
        }
        __syncthreads();
    }
#pragma unroll
    for (int i = 0; i < 4; i++) {
        int n = n0 + ty * 4 + i;
        if (n < NN) {
            float4 v = make_float4(acc[i][0], acc[i][1], acc[i][2], acc[i][3]);
            *(float4*)&g_proj[((size_t)m * NN + n) * DH + tx * 4] = v;
        }
    }
}

// ---------------------------------------------------------------------------
// Kernel 2: scatter edges: g_h[m][dst] += g_proj[m][src]; degree count.
// 16 threads per edge, float4 per thread, red.global.add.v4.f32.
// ---------------------------------------------------------------------------
__global__ __launch_bounds__(256) void scatter_kernel(const int* __restrict__ src,
                                                      const int* __restrict__ dst) {
    long long gid = (long long)blockIdx.x * blockDim.x + threadIdx.x;
    long long e = gid >> 4;
    if (e >= (long long)M3 * NE) return;
    int part = (int)(gid & 15);
    int m  = (int)(e / NE);
    int ei = (int)(e - (long long)m * NE);
    int s = src[(size_t)m * NE + ei];
    int d = dst[(size_t)m * NE + ei];
    float4 v = *(const float4*)(g_proj + ((size_t)m * NN + s) * DH + part * 4);
    float* p = g_h + ((size_t)m * NN + d) * DH + part * 4;
    asm volatile("red.global.add.v4.f32 [%0], {%1,%2,%3,%4};"
                 :: "l"(p), "f"(v.x), "f"(v.y), "f"(v.z), "f"(v.w) : "memory");
    if (part == 0) atomicAdd(&g_deg[(size_t)m * NN + d], 1.0f);
}

// ---------------------------------------------------------------------------
// Kernel 3: finalize: h = prelu(agg/deg + b); s = tanh(h@fcW + fcb);
// logits[m] += dot(s, attn). One warp per (m,n) pair, grid-stride.
// ---------------------------------------------------------------------------
__global__ __launch_bounds__(256) void finalize_kernel(const float* __restrict__ b,
                                                       const float* __restrict__ prelu_a,
                                                       const float* __restrict__ fc_W,
                                                       const float* __restrict__ fc_b,
                                                       const float* __restrict__ attn) {
    __shared__ __align__(16) float2 sW2[DH][32];   // (fcW[k][c], fcW[k][c+32])
    __shared__ __align__(16) float  sh[8][DH];
    __shared__ float sLog[M3];
    const int tid = threadIdx.x;
    const int wid = tid >> 5, lane = tid & 31;

    for (int i = tid; i < DH * 32; i += 256) {
        int k = i >> 5, c = i & 31;
        sW2[k][c] = make_float2(fc_W[k * DH + c], fc_W[k * DH + c + 32]);
    }
    if (tid < M3) sLog[tid] = 0.f;
    __syncthreads();

    const float fcb0 = fc_b[lane],      fcb1 = fc_b[lane + 32];
    const float at0  = attn[lane],      at1  = attn[lane + 32];

    const int totalWarps = gridDim.x * (blockDim.x >> 5);
    int gw = blockIdx.x * (blockDim.x >> 5) + wid;
    float log0 = 0.f, log1 = 0.f, log2 = 0.f;

    for (long long p = gw; p < (long long)M3 * NN; p += totalWarps) {
        int m = (int)(p / NN);
        int n = (int)(p - (long long)m * NN);
        size_t base = ((size_t)m * NN + n) * DH;
        float deg = fmaxf(g_deg[(size_t)m * NN + n], 1.0f);
        float a = prelu_a[m];
        float inv = 1.0f / deg;
        float h0 = g_h[base + lane]      * inv + b[m * DH + lane];
        float h1 = g_h[base + lane + 32] * inv + b[m * DH + lane + 32];
        h0 = (h0 > 0.f) ? h0 : a * h0;
        h1 = (h1 > 0.f) ? h1 : a * h1;
        g_h[base + lane]      = h0;
        g_h[base + lane + 32] = h1;
        sh[wid][lane]      = h0;
        sh[wid][lane + 32] = h1;
        __syncwarp();
        float acc0 = fcb0, acc1 = fcb1;
#pragma unroll
        for (int k = 0; k < DH; k += 2) {
            float2 hk = *(const float2*)&sh[wid][k];
            float2 w0 = sW2[k][lane];
            float2 w1 = sW2[k + 1][lane];
            acc0 += hk.x * w0.x; acc1 += hk.x * w0.y;
            acc0 += hk.y * w1.x; acc1 += hk.y * w1.y;
        }
        float s0 = tanhf(acc0), s1 = tanhf(acc1);
        float part = s0 * at0 + s1 * at1;
#pragma unroll
        for (int o = 16; o; o >>= 1) part += __shfl_down_sync(0xffffffffu, part, o);
        if (lane == 0) {
            if (m == 0)      log0 += part;
            else if (m == 1) log1 += part;
            else             log2 += part;
        }
        __syncwarp();
    }
    if (lane == 0) {
        if (log0 != 0.f) atomicAdd(&sLog[0], log0);
        if (log1 != 0.f) atomicAdd(&sLog[1], log1);
        if (log2 != 0.f) atomicAdd(&sLog[2], log2);
    }
    __syncthreads();
    if (tid < M3) atomicAdd(&g_logits[tid], sLog[tid]);
}

// ---------------------------------------------------------------------------
// Kernel 4: beta = softmax(logits / N)
// ---------------------------------------------------------------------------
__global__ void beta_kernel() {
    if (threadIdx.x == 0) {
        float l0 = g_logits[0] / (float)NN;
        float l1 = g_logits[1] / (float)NN;
        float l2 = g_logits[2] / (float)NN;
        float mx = fmaxf(l0, fmaxf(l1, l2));
        float e0 = expf(l0 - mx), e1 = expf(l1 - mx), e2 = expf(l2 - mx);
        float s = e0 + e1 + e2;
        g_beta[0] = e0 / s; g_beta[1] = e1 / s; g_beta[2] = e2 / s;
    }
}

// ---------------------------------------------------------------------------
// Kernel 5: z[n][h] = sum_m beta[m] * h[m][n][h]
// ---------------------------------------------------------------------------
__global__ __launch_bounds__(256) void z_kernel(float* __restrict__ out) {
    size_t i = (size_t)blockIdx.x * blockDim.x + threadIdx.x;
    size_t tot = (size_t)NN * DH / 4;
    if (i >= tot) return;
    float b0 = g_beta[0], b1 = g_beta[1], b2 = g_beta[2];
    float4 h0 = ((const float4*)(g_h + (size_t)0 * NN * DH))[i];
    float4 h1 = ((const float4*)(g_h + (size_t)1 * NN * DH))[i];
    float4 h2 = ((const float4*)(g_h + (size_t)2 * NN * DH))[i];
    float4 r;
    r.x = b0 * h0.x + b1 * h1.x + b2 * h2.x;
    r.y = b0 * h0.y + b1 * h1.y + b2 * h2.y;
    r.z = b0 * h0.z + b1 * h1.z + b2 * h2.z;
    r.w = b0 * h0.w + b1 * h1.w + b2 * h2.w;
    ((float4*)out)[i] = r;
}

// ---------------------------------------------------------------------------
extern "C" void kernel_launch(void* const* d_in, const int* in_sizes, int n_in,
                              void* d_out, int out_size) {
    const float* feats   = (const float*)d_in[0];
    const int*   src     = (const int*)  d_in[1];
    const int*   dst     = (const int*)  d_in[2];
    const float* W       = (const float*)d_in[3];
    const float* b       = (const float*)d_in[4];
    const float* prelu_a = (const float*)d_in[5];
    const float* fc_W    = (const float*)d_in[6];
    const float* fc_b    = (const float*)d_in[7];
    const float* attn    = (const float*)d_in[8];
    float* out = (float*)d_out;

    // 0) zero scratch
    {
        size_t tot4 = (size_t)M3 * NN * DH / 4;
        int grid = (int)((tot4 + 255) / 256);
        zero_kernel<<<grid, 256>>>();
    }
    // 1) proj GEMM
    {
        dim3 grid((NN + 63) / 64, M3);
        proj_kernel<<<grid, 256>>>(feats, W);
    }
    // 2) scatter + degree
    {
        long long threads = (long long)M3 * NE * 16;
        int grid = (int)((threads + 255) / 256);
        scatter_kernel<<<grid, 256>>>(src, dst);
    }
    // 3) finalize (h, tanh matvec, logits)
    finalize_kernel<<<2048, 256>>>(b, prelu_a, fc_W, fc_b, attn);
    // 4) beta
    beta_kernel<<<1, 32>>>();
    // 5) z
    {
        size_t tot = (size_t)NN * DH / 4;
        int grid = (int)((tot + 255) / 256);
        z_kernel<<<grid, 256>>>(out);
    }
}

// round 2
// speedup vs baseline: 1.1172x; 1.1172x over previous
#include <cuda_runtime.h>
#include <cuda_bf16.h>
#include <math.h>

#define NN   100000
#define M3   3
#define DIN  128
#define DH   64
#define NE   1600000

// ---- scratch (static device allocations; no cudaMalloc allowed) ----
__device__ float g_proj[(size_t)M3 * NN * DH];   // [m][n][h]
__device__ float g_h   [(size_t)M3 * NN * DH];   // agg, then post-prelu h
__device__ float g_deg [(size_t)M3 * NN];
__device__ float g_logits[M3];
__device__ float g_beta[M3];

// ---------------------------------------------------------------------------
// Kernel 0: zero agg/deg/logits
// ---------------------------------------------------------------------------
__global__ void zero_kernel() {
    size_t i = (size_t)blockIdx.x * blockDim.x + threadIdx.x;
    size_t tot4 = (size_t)M3 * NN * DH / 4;           // 4.8M float4
    if (i < tot4) ((float4*)g_h)[i] = make_float4(0.f, 0.f, 0.f, 0.f);
    if (i < (size_t)M3 * NN / 4) ((float4*)g_deg)[i] = make_float4(0.f, 0.f, 0.f, 0.f);
    if (i == 0) { g_logits[0] = 0.f; g_logits[1] = 0.f; g_logits[2] = 0.f; }
}

// ---------------------------------------------------------------------------
// Kernel 1: proj[m][n][h] = sum_d feats[m][n][d] * W[m][d][h]
// 64x64 output tile per block, 256 threads, 4x4 microtile, k-chunks of 64.
// ---------------------------------------------------------------------------
__global__ __launch_bounds__(256) void proj_kernel(const float* __restrict__ feats,
                                                   const float* __restrict__ W) {
    __shared__ __align__(16) float sF[64][65];   // [node][k] padded
    __shared__ __align__(16) float sW[64][DH];   // [k][h]
    const int m  = blockIdx.y;
    const int n0 = blockIdx.x * 64;
    const int tid = threadIdx.x;
    const int tx = tid & 15, ty = tid >> 4;

    const float* fbase = feats + (size_t)m * NN * DIN;
    const float* wbase = W + (size_t)m * DIN * DH;

    float acc[4][4] = {};
    for (int kk = 0; kk < DIN; kk += 64) {
        for (int i = tid; i < 64 * 64; i += 256) {
            int r = i >> 6, c = i & 63;
            int n = n0 + r;
            sF[r][c] = (n < NN) ? fbase[(size_t)n * DIN + kk + c] : 0.f;
        }
        for (int i = tid; i < 64 * DH; i += 256) {
            int r = i >> 6, c = i & 63;
            sW[r][c] = wbase[(size_t)(kk + r) * DH + c];
        }
        __syncthreads();
#pragma unroll
        for (int k = 0; k < 64; k++) {
            float a0 = sF[ty * 4 + 0][k];
            float a1 = sF[ty * 4 + 1][k];
            float a2 = sF[ty * 4 + 2][k];
            float a3 = sF[ty * 4 + 3][k];
            float4 bv = *(const float4*)&sW[k][tx * 4];
            acc[0][0] += a0 * bv.x; acc[0][1] += a0 * bv.y; acc[0][2] += a0 * bv.z; acc[0][3] += a0 * bv.w;
            acc[1][0] += a1 * bv.x; acc[1][1] += a1 * bv.y; acc[1][2] += a1 * bv.z; acc[1][3] += a1 * bv.w;
            acc[2][0] += a2 * bv.x; acc[2][1] += a2 * bv.y; acc[2][2] += a2 * bv.z; acc[2][3] += a2 * bv.w;
            acc[3][0] += a3 * bv.x; acc[3][1] += a3 * bv.y; acc[3][2] += a3 * bv.z; acc[3][3] += a3 * bv.w;
        }
        __syncthreads();
    }
#pragma unroll
    for (int i = 0; i < 4; i++) {
        int n = n0 + ty * 4 + i;
        if (n < NN) {
            float4 v = make_float4(acc[i][0], acc[i][1], acc[i][2], acc[i][3]);
            *(float4*)&g_proj[((size_t)m * NN + n) * DH + tx * 4] = v;
        }
    }
}

// ---------------------------------------------------------------------------
// Kernel 2: scatter edges: g_h[m][dst] += g_proj[m][src]; degree count.
// 16 threads per edge, float4 per thread, red.global.add.v4.f32.
// ---------------------------------------------------------------------------
__global__ __launch_bounds__(256) void scatter_kernel(const int* __restrict__ src,
                                                      const int* __restrict__ dst) {
    long long gid = (long long)blockIdx.x * blockDim.x + threadIdx.x;
    long long e = gid >> 4;
    if (e >= (long long)M3 * NE) return;
    int part = (int)(gid & 15);
    int m  = (int)(e / NE);
    int ei = (int)(e - (long long)m * NE);
    int s = src[(size_t)m * NE + ei];
    int d = dst[(size_t)m * NE + ei];
    float4 v = *(const float4*)(g_proj + ((size_t)m * NN + s) * DH + part * 4);
    float* p = g_h + ((size_t)m * NN + d) * DH + part * 4;
    asm volatile("red.global.add.v4.f32 [%0], {%1,%2,%3,%4};"
                 :: "l"(p), "f"(v.x), "f"(v.y), "f"(v.z), "f"(v.w) : "memory");
    if (part == 0) atomicAdd(&g_deg[(size_t)m * NN + d], 1.0f);
}

// ---------------------------------------------------------------------------
// Kernel 3: finalize v2: 4 nodes per warp per iteration; weight LDS amortized.
// h = prelu(agg/deg + b); s = tanh(h@fcW + fcb); logits[m] += dot(s, attn).
// ---------------------------------------------------------------------------
__global__ __launch_bounds__(256) void finalize_kernel(const float* __restrict__ b,
                                                       const float* __restrict__ prelu_a,
                                                       const float* __restrict__ fc_W,
                                                       const float* __restrict__ fc_b,
                                                       const float* __restrict__ attn) {
    // sW4[kk][c] = (fcW[2kk][c], fcW[2kk][c+32], fcW[2kk+1][c], fcW[2kk+1][c+32])
    __shared__ __align__(16) float4 sW4[DH / 2][32];
    __shared__ __align__(16) float  sh[8][4][DH];
    __shared__ float sLog[M3];
    const int tid = threadIdx.x;
    const int wid = tid >> 5, lane = tid & 31;

    for (int i = tid; i < (DH / 2) * 32; i += 256) {
        int kk = i >> 5, c = i & 31;
        int k = kk * 2;
        sW4[kk][c] = make_float4(fc_W[k * DH + c],       fc_W[k * DH + c + 32],
                                 fc_W[(k + 1) * DH + c], fc_W[(k + 1) * DH + c + 32]);
    }
    if (tid < M3) sLog[tid] = 0.f;
    __syncthreads();

    const float fcb0 = fc_b[lane],      fcb1 = fc_b[lane + 32];
    const float at0  = attn[lane],      at1  = attn[lane + 32];
    const float a0p = prelu_a[0], a1p = prelu_a[1], a2p = prelu_a[2];

    const long long totalGroups = (long long)M3 * NN / 4;   // 75000
    const int totalWarps = gridDim.x * (blockDim.x >> 5);
    float log0 = 0.f, log1 = 0.f, log2 = 0.f;

    for (long long g = (long long)blockIdx.x * (blockDim.x >> 5) + wid;
         g < totalGroups; g += totalWarps) {
        long long p0 = g * 4;
        int   mj[4];
        float acc0[4], acc1[4];
#pragma unroll
        for (int j = 0; j < 4; j++) {
            long long p = p0 + j;
            int m = (int)(p / NN);
            mj[j] = m;
            size_t base = (size_t)p * DH;            // [m][n][h] with p = m*NN+n
            float inv = 1.0f / fmaxf(g_deg[p], 1.0f);
            float a = (m == 0) ? a0p : (m == 1) ? a1p : a2p;
            float h0 = g_h[base + lane]      * inv + b[m * DH + lane];
            float h1 = g_h[base + lane + 32] * inv + b[m * DH + lane + 32];
            h0 = (h0 > 0.f) ? h0 : a * h0;
            h1 = (h1 > 0.f) ? h1 : a * h1;
            g_h[base + lane]      = h0;
            g_h[base + lane + 32] = h1;
            sh[wid][j][lane]      = h0;
            sh[wid][j][lane + 32] = h1;
            acc0[j] = fcb0; acc1[j] = fcb1;
        }
        __syncwarp();
#pragma unroll
        for (int kk = 0; kk < DH / 2; kk++) {
            float4 w = sW4[kk][lane];
#pragma unroll
            for (int j = 0; j < 4; j++) {
                float2 hk = *(const float2*)&sh[wid][j][kk * 2];  // broadcast
                acc0[j] += hk.x * w.x + hk.y * w.z;
                acc1[j] += hk.x * w.y + hk.y * w.w;
            }
        }
#pragma unroll
        for (int j = 0; j < 4; j++) {
            float part = tanhf(acc0[j]) * at0 + tanhf(acc1[j]) * at1;
#pragma unroll
            for (int o = 16; o; o >>= 1) part += __shfl_down_sync(0xffffffffu, part, o);
            if (lane == 0) {
                if (mj[j] == 0)      log0 += part;
                else if (mj[j] == 1) log1 += part;
                else                 log2 += part;
            }
        }
        __syncwarp();
    }
    if (lane == 0) {
        if (log0 != 0.f) atomicAdd(&sLog[0], log0);
        if (log1 != 0.f) atomicAdd(&sLog[1], log1);
        if (log2 != 0.f) atomicAdd(&sLog[2], log2);
    }
    __syncthreads();
    if (tid < M3) atomicAdd(&g_logits[tid], sLog[tid]);
}

// ---------------------------------------------------------------------------
// Kernel 4: beta = softmax(logits / N)
// ---------------------------------------------------------------------------
__global__ void beta_kernel() {
    if (threadIdx.x == 0) {
        float l0 = g_logits[0] / (float)NN;
        float l1 = g_logits[1] / (float)NN;
        float l2 = g_logits[2] / (float)NN;
        float mx = fmaxf(l0, fmaxf(l1, l2));
        float e0 = expf(l0 - mx), e1 = expf(l1 - mx), e2 = expf(l2 - mx);
        float s = e0 + e1 + e2;
        g_beta[0] = e0 / s; g_beta[1] = e1 / s; g_beta[2] = e2 / s;
    }
}

// ---------------------------------------------------------------------------
// Kernel 5: z[n][h] = sum_m beta[m] * h[m][n][h]
// ---------------------------------------------------------------------------
__global__ __launch_bounds__(256) void z_kernel(float* __restrict__ out) {
    size_t i = (size_t)blockIdx.x * blockDim.x + threadIdx.x;
    size_t tot = (size_t)NN * DH / 4;
    if (i >= tot) return;
    float b0 = g_beta[0], b1 = g_beta[1], b2 = g_beta[2];
    float4 h0 = ((const float4*)(g_h + (size_t)0 * NN * DH))[i];
    float4 h1 = ((const float4*)(g_h + (size_t)1 * NN * DH))[i];
    float4 h2 = ((const float4*)(g_h + (size_t)2 * NN * DH))[i];
    float4 r;
    r.x = b0 * h0.x + b1 * h1.x + b2 * h2.x;
    r.y = b0 * h0.y + b1 * h1.y + b2 * h2.y;
    r.z = b0 * h0.z + b1 * h1.z + b2 * h2.z;
    r.w = b0 * h0.w + b1 * h1.w + b2 * h2.w;
    ((float4*)out)[i] = r;
}

// ---------------------------------------------------------------------------
extern "C" void kernel_launch(void* const* d_in, const int* in_sizes, int n_in,
                              void* d_out, int out_size) {
    const float* feats   = (const float*)d_in[0];
    const int*   src     = (const int*)  d_in[1];
    const int*   dst     = (const int*)  d_in[2];
    const float* W       = (const float*)d_in[3];
    const float* b       = (const float*)d_in[4];
    const float* prelu_a = (const float*)d_in[5];
    const float* fc_W    = (const float*)d_in[6];
    const float* fc_b    = (const float*)d_in[7];
    const float* attn    = (const float*)d_in[8];
    float* out = (float*)d_out;

    // 0) zero scratch
    {
        size_t tot4 = (size_t)M3 * NN * DH / 4;
        int grid = (int)((tot4 + 255) / 256);
        zero_kernel<<<grid, 256>>>();
    }
    // 1) proj GEMM
    {
        dim3 grid((NN + 63) / 64, M3);
        proj_kernel<<<grid, 256>>>(feats, W);
    }
    // 2) scatter + degree
    {
        long long threads = (long long)M3 * NE * 16;
        int grid = (int)((threads + 255) / 256);
        scatter_kernel<<<grid, 256>>>(src, dst);
    }
    // 3) finalize (h, tanh matvec, logits)
    finalize_kernel<<<2048, 256>>>(b, prelu_a, fc_W, fc_b, attn);
    // 4) beta
    beta_kernel<<<1, 32>>>();
    // 5) z
    {
        size_t tot = (size_t)NN * DH / 4;
        int grid = (int)((tot + 255) / 256);
        z_kernel<<<grid, 256>>>(out);
    }
}

// round 4
// speedup vs baseline: 1.1193x; 1.0019x over previous
#include <cuda_runtime.h>
#include <cuda_bf16.h>
#include <math.h>

#define NN   100000
#define M3   3
#define DIN  128
#define DH   64
#define NE   1600000

// ---- scratch (static device allocations; no cudaMalloc allowed) ----
__device__ float g_proj[(size_t)M3 * NN * DH];   // [m][n][h]
__device__ float g_h   [(size_t)M3 * NN * DH];   // agg, then post-prelu h
__device__ float g_deg [(size_t)M3 * NN];
__device__ float g_logits[M3];
__device__ float g_beta[M3];

// ---------------------------------------------------------------------------
// Kernel 0: zero agg/deg/logits
// ---------------------------------------------------------------------------
__global__ void zero_kernel() {
    size_t i = (size_t)blockIdx.x * blockDim.x + threadIdx.x;
    size_t tot4 = (size_t)M3 * NN * DH / 4;           // 4.8M float4
    if (i < tot4) ((float4*)g_h)[i] = make_float4(0.f, 0.f, 0.f, 0.f);
    if (i < (size_t)M3 * NN / 4) ((float4*)g_deg)[i] = make_float4(0.f, 0.f, 0.f, 0.f);
    if (i == 0) { g_logits[0] = 0.f; g_logits[1] = 0.f; g_logits[2] = 0.f; }
}

// ---------------------------------------------------------------------------
// Kernel 1: proj[m][n][h] = sum_d feats[m][n][d] * W[m][d][h]
// 64x64 tile, 256 threads, 4x4 microtile. A-tile stored TRANSPOSED so the
// inner loop is 2x LDS128 per 16 FMA. Row stride 68 (multiple of 4) keeps
// float4 slots 16B-aligned.
// ---------------------------------------------------------------------------
__global__ __launch_bounds__(256) void proj_kernel(const float* __restrict__ feats,
                                                   const float* __restrict__ W) {
    __shared__ __align__(16) float sFT[64][68];  // [k][node], stride 68 (16B aligned)
    __shared__ __align__(16) float sW[64][DH];   // [k][h]
    const int m  = blockIdx.y;
    const int n0 = blockIdx.x * 64;
    const int tid = threadIdx.x;
    const int tx = tid & 15, ty = tid >> 4;

    const float* fbase = feats + (size_t)m * NN * DIN;
    const float* wbase = W + (size_t)m * DIN * DH;

    float acc[4][4] = {};
    for (int kk = 0; kk < DIN; kk += 64) {
        for (int i = tid; i < 64 * 64; i += 256) {
            int r = i >> 6, c = i & 63;          // r = node-in-tile, c = k-in-chunk
            int n = n0 + r;
            sFT[c][r] = (n < NN) ? fbase[(size_t)n * DIN + kk + c] : 0.f;
        }
        for (int i = tid; i < 64 * DH; i += 256) {
            int r = i >> 6, c = i & 63;
            sW[r][c] = wbase[(size_t)(kk + r) * DH + c];
        }
        __syncthreads();
#pragma unroll
        for (int k = 0; k < 64; k++) {
            float4 av = *(const float4*)&sFT[k][ty * 4];
            float4 bv = *(const float4*)&sW[k][tx * 4];
            acc[0][0] += av.x * bv.x; acc[0][1] += av.x * bv.y; acc[0][2] += av.x * bv.z; acc[0][3] += av.x * bv.w;
            acc[1][0] += av.y * bv.x; acc[1][1] += av.y * bv.y; acc[1][2] += av.y * bv.z; acc[1][3] += av.y * bv.w;
            acc[2][0] += av.z * bv.x; acc[2][1] += av.z * bv.y; acc[2][2] += av.z * bv.z; acc[2][3] += av.z * bv.w;
            acc[3][0] += av.w * bv.x; acc[3][1] += av.w * bv.y; acc[3][2] += av.w * bv.z; acc[3][3] += av.w * bv.w;
        }
        __syncthreads();
    }
#pragma unroll
    for (int i = 0; i < 4; i++) {
        int n = n0 + ty * 4 + i;
        if (n < NN) {
            float4 v = make_float4(acc[i][0], acc[i][1], acc[i][2], acc[i][3]);
            *(float4*)&g_proj[((size_t)m * NN + n) * DH + tx * 4] = v;
        }
    }
}

// ---------------------------------------------------------------------------
// Kernel 2: scatter edges: g_h[m][dst] += g_proj[m][src]; degree count.
// 16 threads per edge, float4 per thread, red.global.add.v4.f32.
// ---------------------------------------------------------------------------
__global__ __launch_bounds__(256) void scatter_kernel(const int* __restrict__ src,
                                                      const int* __restrict__ dst) {
    long long gid = (long long)blockIdx.x * blockDim.x + threadIdx.x;
    long long e = gid >> 4;
    if (e >= (long long)M3 * NE) return;
    int part = (int)(gid & 15);
    int m  = (int)(e / NE);
    int ei = (int)(e - (long long)m * NE);
    int s = src[(size_t)m * NE + ei];
    int d = dst[(size_t)m * NE + ei];
    float4 v = *(const float4*)(g_proj + ((size_t)m * NN + s) * DH + part * 4);
    float* p = g_h + ((size_t)m * NN + d) * DH + part * 4;
    asm volatile("red.global.add.v4.f32 [%0], {%1,%2,%3,%4};"
                 :: "l"(p), "f"(v.x), "f"(v.y), "f"(v.z), "f"(v.w) : "memory");
    if (part == 0) atomicAdd(&g_deg[(size_t)m * NN + d], 1.0f);
}

// ---------------------------------------------------------------------------
// Kernel 3: finalize v3: 8 nodes/warp/iter; k packed float4; lane owns cols
// (2*lane, 2*lane+1). h = prelu(agg/deg + b); s = tanh(h@fcW + fcb);
// logits[m] += dot(s, attn).
// ---------------------------------------------------------------------------
__global__ __launch_bounds__(256) void finalize_kernel(const float* __restrict__ b,
                                                       const float* __restrict__ prelu_a,
                                                       const float* __restrict__ fc_W,
                                                       const float* __restrict__ fc_b,
                                                       const float* __restrict__ attn) {
    // sWA[kk][c].{x,y,z,w} = fcW[4kk+i][2c];  sWB same for column 2c+1
    __shared__ __align__(16) float4 sWA[DH / 4][32];
    __shared__ __align__(16) float4 sWB[DH / 4][32];
    __shared__ __align__(16) float  sh[8][8][DH];   // [warp][j][k]
    __shared__ float sLog[M3];
    const int tid = threadIdx.x;
    const int wid = tid >> 5, lane = tid & 31;

    for (int i = tid; i < (DH / 4) * 32; i += 256) {
        int kk = i >> 5, c = i & 31;
        int k0 = kk * 4;
        sWA[kk][c] = make_float4(fc_W[(k0 + 0) * DH + 2 * c], fc_W[(k0 + 1) * DH + 2 * c],
                                 fc_W[(k0 + 2) * DH + 2 * c], fc_W[(k0 + 3) * DH + 2 * c]);
        sWB[kk][c] = make_float4(fc_W[(k0 + 0) * DH + 2 * c + 1], fc_W[(k0 + 1) * DH + 2 * c + 1],
                                 fc_W[(k0 + 2) * DH + 2 * c + 1], fc_W[(k0 + 3) * DH + 2 * c + 1]);
    }
    if (tid < M3) sLog[tid] = 0.f;
    __syncthreads();

    const float2 fcb2 = *(const float2*)&fc_b[2 * lane];
    const float2 at2  = *(const float2*)&attn[2 * lane];
    const float a0p = prelu_a[0], a1p = prelu_a[1], a2p = prelu_a[2];

    const long long totalGroups = (long long)M3 * NN / 8;   // 37500, never crosses m
    const int totalWarps = gridDim.x * (blockDim.x >> 5);
    float log0 = 0.f, log1 = 0.f, log2 = 0.f;

    for (long long g = (long long)blockIdx.x * (blockDim.x >> 5) + wid;
         g < totalGroups; g += totalWarps) {
        long long p0 = g * 8;
        const int m = (int)(p0 / NN);                   // constant over j (8 | NN)
        const float a = (m == 0) ? a0p : (m == 1) ? a1p : a2p;
        const float2 bb = *(const float2*)&b[m * DH + 2 * lane];
        float acc0[8], acc1[8];
#pragma unroll
        for (int j = 0; j < 8; j++) {
            long long p = p0 + j;
            size_t base = (size_t)p * DH;
            float inv = 1.0f / fmaxf(g_deg[p], 1.0f);
            float2 h2 = *(const float2*)&g_h[base + 2 * lane];
            h2.x = h2.x * inv + bb.x;
            h2.y = h2.y * inv + bb.y;
            h2.x = (h2.x > 0.f) ? h2.x : a * h2.x;
            h2.y = (h2.y > 0.f) ? h2.y : a * h2.y;
            *(float2*)&g_h[base + 2 * lane] = h2;
            *(float2*)&sh[wid][j][2 * lane] = h2;
            acc0[j] = fcb2.x; acc1[j] = fcb2.y;
        }
        __syncwarp();
#pragma unroll
        for (int kk = 0; kk < DH / 4; kk++) {
            float4 wa = sWA[kk][lane];
            float4 wb = sWB[kk][lane];
#pragma unroll
            for (int j = 0; j < 8; j++) {
                float4 hk = *(const float4*)&sh[wid][j][kk * 4];  // broadcast
                acc0[j] += hk.x * wa.x + hk.y * wa.y + hk.z * wa.z + hk.w * wa.w;
                acc1[j] += hk.x * wb.x + hk.y * wb.y + hk.z * wb.z + hk.w * wb.w;
            }
        }
        float lsum = 0.f;
#pragma unroll
        for (int j = 0; j < 8; j++) {
            float part = tanhf(acc0[j]) * at2.x + tanhf(acc1[j]) * at2.y;
#pragma unroll
            for (int o = 16; o; o >>= 1) part += __shfl_down_sync(0xffffffffu, part, o);
            lsum += part;
        }
        if (lane == 0) {
            if (m == 0)      log0 += lsum;
            else if (m == 1) log1 += lsum;
            else             log2 += lsum;
        }
        __syncwarp();
    }
    if (lane == 0) {
        if (log0 != 0.f) atomicAdd(&sLog[0], log0);
        if (log1 != 0.f) atomicAdd(&sLog[1], log1);
        if (log2 != 0.f) atomicAdd(&sLog[2], log2);
    }
    __syncthreads();
    if (tid < M3) atomicAdd(&g_logits[tid], sLog[tid]);
}

// ---------------------------------------------------------------------------
// Kernel 4: beta = softmax(logits / N)
// ---------------------------------------------------------------------------
__global__ void beta_kernel() {
    if (threadIdx.x == 0) {
        float l0 = g_logits[0] / (float)NN;
        float l1 = g_logits[1] / (float)NN;
        float l2 = g_logits[2] / (float)NN;
        float mx = fmaxf(l0, fmaxf(l1, l2));
        float e0 = expf(l0 - mx), e1 = expf(l1 - mx), e2 = expf(l2 - mx);
        float s = e0 + e1 + e2;
        g_beta[0] = e0 / s; g_beta[1] = e1 / s; g_beta[2] = e2 / s;
    }
}

// ---------------------------------------------------------------------------
// Kernel 5: z[n][h] = sum_m beta[m] * h[m][n][h]
// ---------------------------------------------------------------------------
__global__ __launch_bounds__(256) void z_kernel(float* __restrict__ out) {
    size_t i = (size_t)blockIdx.x * blockDim.x + threadIdx.x;
    size_t tot = (size_t)NN * DH / 4;
    if (i >= tot) return;
    float b0 = g_beta[0], b1 = g_beta[1], b2 = g_beta[2];
    float4 h0 = ((const float4*)(g_h + (size_t)0 * NN * DH))[i];
    float4 h1 = ((const float4*)(g_h + (size_t)1 * NN * DH))[i];
    float4 h2 = ((const float4*)(g_h + (size_t)2 * NN * DH))[i];
    float4 r;
    r.x = b0 * h0.x + b1 * h1.x + b2 * h2.x;
    r.y = b0 * h0.y + b1 * h1.y + b2 * h2.y;
    r.z = b0 * h0.z + b1 * h1.z + b2 * h2.z;
    r.w = b0 * h0.w + b1 * h1.w + b2 * h2.w;
    ((float4*)out)[i] = r;
}

// ---------------------------------------------------------------------------
extern "C" void kernel_launch(void* const* d_in, const int* in_sizes, int n_in,
                              void* d_out, int out_size) {
    const float* feats   = (const float*)d_in[0];
    const int*   src     = (const int*)  d_in[1];
    const int*   dst     = (const int*)  d_in[2];
    const float* W       = (const float*)d_in[3];
    const float* b       = (const float*)d_in[4];
    const float* prelu_a = (const float*)d_in[5];
    const float* fc_W    = (const float*)d_in[6];
    const float* fc_b    = (const float*)d_in[7];
    const float* attn    = (const float*)d_in[8];
    float* out = (float*)d_out;

    // 0) zero scratch
    {
        size_t tot4 = (size_t)M3 * NN * DH / 4;
        int grid = (int)((tot4 + 255) / 256);
        zero_kernel<<<grid, 256>>>();
    }
    // 1) proj GEMM
    {
        dim3 grid((NN + 63) / 64, M3);
        proj_kernel<<<grid, 256>>>(feats, W);
    }
    // 2) scatter + degree
    {
        long long threads = (long long)M3 * NE * 16;
        int grid = (int)((threads + 255) / 256);
        scatter_kernel<<<grid, 256>>>(src, dst);
    }
    // 3) finalize (h, tanh matvec, logits)
    finalize_kernel<<<296, 256>>>(b, prelu_a, fc_W, fc_b, attn);
    // 4) beta
    beta_kernel<<<1, 32>>>();
    // 5) z
    {
        size_t tot = (size_t)NN * DH / 4;
        int grid = (int)((tot + 255) / 256);
        z_kernel<<<grid, 256>>>(out);
    }
}